// round 5
// baseline (speedup 1.0000x reference)
#include <cuda_runtime.h>
#include <cstdint>

#define N 256
#define NP 65536u
#define NVOX 16777216u

// Packed xy-box intermediates: float4{sum_i,sum_r,sum_ii,sum_rr} + float{sum_ir}
__device__ float4 g_sum4[16777216];
__device__ float  g_sum1[16777216];

__global__ void marker_kernel() {}

// ===========================================================================
// Kernel 1: 5x5 box in X (warp shuffles) and Y (per-thread register ring).
// One-row-ahead register prefetch hides load latency.
// ===========================================================================
#define K1_YC 64

__global__ __launch_bounds__(256) void boxxy_kernel(
    const float* __restrict__ img, const float* __restrict__ ref)
{
    const unsigned FULL = 0xFFFFFFFFu;
    const int lane = threadIdx.x & 31;
    const int x = threadIdx.x;                 // 0..255 (warp spans 32 x)
    const int z = blockIdx.x;
    const int y0 = blockIdx.y * K1_YC;
    const unsigned zoff = (unsigned)z * NP;

    const bool lm2 = (lane < 2);
    const bool lm1 = (lane == 0);
    const bool lp2 = (lane >= 30);
    const bool lp1 = (lane == 31);

    float qi[5], qr[5], qii[5], qrr[5], qir[5];
#pragma unroll
    for (int k = 0; k < 5; k++) qi[k] = qr[k] = qii[k] = qrr[k] = qir[k] = 0.f;

    // --- prefetch row t=0 (y = y0-2) ---
    float p_vi, p_vr, p_m2i, p_m1i, p_p2i, p_p1i, p_m2r, p_m1r, p_p2r, p_p1r;
    {
        const int yy = y0 - 2;
        const bool in = (yy >= 0);
        const unsigned rb = zoff + (unsigned)(in ? yy : 0) * N;
        p_vi  = in ? __ldg(img + rb + x) : 0.f;
        p_vr  = in ? __ldg(ref + rb + x) : 0.f;
        p_m2i = (lm2 && in && x >= 2)    ? __ldg(img + rb + x - 2) : 0.f;
        p_m1i = (lm1 && in && x >= 1)    ? __ldg(img + rb + x - 1) : 0.f;
        p_p2i = (lp2 && in && x + 2 < N) ? __ldg(img + rb + x + 2) : 0.f;
        p_p1i = (lp1 && in && x + 1 < N) ? __ldg(img + rb + x + 1) : 0.f;
        p_m2r = (lm2 && in && x >= 2)    ? __ldg(ref + rb + x - 2) : 0.f;
        p_m1r = (lm1 && in && x >= 1)    ? __ldg(ref + rb + x - 1) : 0.f;
        p_p2r = (lp2 && in && x + 2 < N) ? __ldg(ref + rb + x + 2) : 0.f;
        p_p1r = (lp1 && in && x + 1 < N) ? __ldg(ref + rb + x + 1) : 0.f;
    }

    for (int t = 0; t < K1_YC + 4; ++t) {
        // consume prefetched row
        const float vi = p_vi, vr = p_vr;
        const float e_m2i = p_m2i, e_m1i = p_m1i, e_p2i = p_p2i, e_p1i = p_p1i;
        const float e_m2r = p_m2r, e_m1r = p_m1r, e_p2r = p_p2r, e_p1r = p_p1r;

        // issue prefetch for next row
        if (t + 1 < K1_YC + 4) {
            const int yy = y0 - 1 + t;
            const bool in = (yy >= 0) & (yy < N);
            const unsigned rb = zoff + (unsigned)(in ? yy : 0) * N;
            p_vi  = in ? __ldg(img + rb + x) : 0.f;
            p_vr  = in ? __ldg(ref + rb + x) : 0.f;
            p_m2i = (lm2 && in && x >= 2)    ? __ldg(img + rb + x - 2) : 0.f;
            p_m1i = (lm1 && in && x >= 1)    ? __ldg(img + rb + x - 1) : 0.f;
            p_p2i = (lp2 && in && x + 2 < N) ? __ldg(img + rb + x + 2) : 0.f;
            p_p1i = (lp1 && in && x + 1 < N) ? __ldg(img + rb + x + 1) : 0.f;
            p_m2r = (lm2 && in && x >= 2)    ? __ldg(ref + rb + x - 2) : 0.f;
            p_m1r = (lm1 && in && x >= 1)    ? __ldg(ref + rb + x - 1) : 0.f;
            p_p2r = (lp2 && in && x + 2 < N) ? __ldg(ref + rb + x + 2) : 0.f;
            p_p1r = (lp1 && in && x + 1 < N) ? __ldg(ref + rb + x + 1) : 0.f;
        }

        float vim1 = __shfl_up_sync(FULL, vi, 1);
        float vim2 = __shfl_up_sync(FULL, vi, 2);
        float vip1 = __shfl_down_sync(FULL, vi, 1);
        float vip2 = __shfl_down_sync(FULL, vi, 2);
        float rim1 = __shfl_up_sync(FULL, vr, 1);
        float rim2 = __shfl_up_sync(FULL, vr, 2);
        float rip1 = __shfl_down_sync(FULL, vr, 1);
        float rip2 = __shfl_down_sync(FULL, vr, 2);

        if (lm2) { vim2 = e_m2i; rim2 = e_m2r; }
        if (lm1) { vim1 = e_m1i; rim1 = e_m1r; }
        if (lp2) { vip2 = e_p2i; rip2 = e_p2r; }
        if (lp1) { vip1 = e_p1i; rip1 = e_p1r; }

        const float s_i  = vim2 + vim1 + vi + vip1 + vip2;
        const float s_r  = rim2 + rim1 + vr + rip1 + rip2;
        const float s_ii = vim2*vim2 + vim1*vim1 + vi*vi + vip1*vip1 + vip2*vip2;
        const float s_rr = rim2*rim2 + rim1*rim1 + vr*vr + rip1*rip1 + rip2*rip2;
        const float s_ir = vim2*rim2 + vim1*rim1 + vi*vr + vip1*rip1 + vip2*rip2;

#pragma unroll
        for (int k = 0; k < 4; k++) {
            qi[k] = qi[k+1]; qr[k] = qr[k+1]; qii[k] = qii[k+1];
            qrr[k] = qrr[k+1]; qir[k] = qir[k+1];
        }
        qi[4] = s_i; qr[4] = s_r; qii[4] = s_ii; qrr[4] = s_rr; qir[4] = s_ir;

        if (t >= 4) {
            const unsigned o = zoff + (unsigned)(y0 + t - 4) * N + (unsigned)x;
            float4 v;
            v.x = qi[0] + qi[1] + qi[2] + qi[3] + qi[4];
            v.y = qr[0] + qr[1] + qr[2] + qr[3] + qr[4];
            v.z = qii[0] + qii[1] + qii[2] + qii[3] + qii[4];
            v.w = qrr[0] + qrr[1] + qrr[2] + qrr[3] + qrr[4];
            g_sum4[o] = v;
            g_sum1[o] = qir[0] + qir[1] + qir[2] + qir[3] + qir[4];
        }
    }
}

// ===========================================================================
// Kernel 2: z-box + gradients + force epilogue. 2 voxels (x pair) per thread,
// one-plane-ahead register prefetch, 5-deep register rings.
// CTA: 256 threads = 2 y-rows x 128 x-pairs. Marches 32-plane z chunk.
// ===========================================================================
#define K2_ZC 32

__global__ __launch_bounds__(256, 2) void zbox_final_kernel(
    const float* __restrict__ img, const float* __restrict__ ref,
    float* __restrict__ out)
{
    const unsigned FULL = 0xFFFFFFFFu;
    const int tid  = threadIdx.x;
    const int lane = tid & 31;
    const int xi   = tid & 127;          // x-pair index, 0..127
    const int x0   = xi << 1;            // first x of pair
    const int y    = (blockIdx.x << 1) + (tid >> 7);
    const int z0   = blockIdx.y * K2_ZC;
    const unsigned base = (unsigned)y * N + (unsigned)x0;

    const float npix = 125.0f;
    const float inv_npix = 1.0f / 125.0f;

    float4 A4[5], B4[5];      // sums for x0, x0+1
    float2 S1[5];             // sum_ir pair
    float2 Ci[3], Cr[3];      // center pairs: planes z-1, z, z+1 (after shift)

    // prologue: slots 1..4 = planes z0-2 .. z0+1
#pragma unroll
    for (int k = 0; k < 4; k++) {
        int zz = z0 - 2 + k;
        bool in = (zz >= 0) & (zz < N);
        unsigned o = (unsigned)(in ? zz : 0) * NP + base;
        A4[k+1] = in ? __ldg(&g_sum4[o])     : make_float4(0.f,0.f,0.f,0.f);
        B4[k+1] = in ? __ldg(&g_sum4[o + 1]) : make_float4(0.f,0.f,0.f,0.f);
        S1[k+1] = in ? *(const float2*)&g_sum1[o] : make_float2(0.f,0.f);
    }
    {
        bool inm = (z0 - 1) >= 0;
        unsigned om = (unsigned)(inm ? (z0 - 1) : 0) * NP + base;
        Ci[1] = inm ? __ldg((const float2*)(img + om)) : make_float2(0.f,0.f);
        Cr[1] = inm ? __ldg((const float2*)(ref + om)) : make_float2(0.f,0.f);
        unsigned oc = (unsigned)z0 * NP + base;
        Ci[2] = __ldg((const float2*)(img + oc));
        Cr[2] = __ldg((const float2*)(ref + oc));
    }
    // pending: sums plane z0+2, centers plane z0+1
    float4 pA, pB; float2 pS, pCi, pCr;
    {
        int zz = z0 + 2;
        bool in = zz < N;
        unsigned o = (unsigned)(in ? zz : 0) * NP + base;
        pA = in ? __ldg(&g_sum4[o])     : make_float4(0.f,0.f,0.f,0.f);
        pB = in ? __ldg(&g_sum4[o + 1]) : make_float4(0.f,0.f,0.f,0.f);
        pS = in ? *(const float2*)&g_sum1[o] : make_float2(0.f,0.f);
        int zc = z0 + 1;
        bool inc = zc < N;
        unsigned oc = (unsigned)(inc ? zc : 0) * NP + base;
        pCi = inc ? __ldg((const float2*)(img + oc)) : make_float2(0.f,0.f);
        pCr = inc ? __ldg((const float2*)(ref + oc)) : make_float2(0.f,0.f);
    }

    for (int z = z0; z < z0 + K2_ZC; ++z) {
        // shift rings, consume pending
#pragma unroll
        for (int k = 0; k < 4; k++) { A4[k] = A4[k+1]; B4[k] = B4[k+1]; S1[k] = S1[k+1]; }
        A4[4] = pA; B4[4] = pB; S1[4] = pS;
        Ci[0] = Ci[1]; Ci[1] = Ci[2]; Ci[2] = pCi;
        Cr[0] = Cr[1]; Cr[1] = Cr[2]; Cr[2] = pCr;

        // issue prefetch for next iteration (sums z+3, centers z+2)
        {
            int zz = z + 3;
            bool in = zz < N;
            unsigned o = (unsigned)(in ? zz : 0) * NP + base;
            pA = in ? __ldg(&g_sum4[o])     : make_float4(0.f,0.f,0.f,0.f);
            pB = in ? __ldg(&g_sum4[o + 1]) : make_float4(0.f,0.f,0.f,0.f);
            pS = in ? *(const float2*)&g_sum1[o] : make_float2(0.f,0.f);
            int zc = z + 2;
            bool inc = zc < N;
            unsigned oc = (unsigned)(inc ? zc : 0) * NP + base;
            pCi = inc ? __ldg((const float2*)(img + oc)) : make_float2(0.f,0.f);
            pCr = inc ? __ldg((const float2*)(ref + oc)) : make_float2(0.f,0.f);
        }

        const unsigned idx = (unsigned)z * NP + base;

        // x-neighbor values outside the pair via shuffle; warp-edge lanes load
        float xm_i = __shfl_up_sync(FULL, Ci[1].y, 1);
        float xm_r = __shfl_up_sync(FULL, Cr[1].y, 1);
        float xp_i = __shfl_down_sync(FULL, Ci[1].x, 1);
        float xp_r = __shfl_down_sync(FULL, Cr[1].x, 1);
        if (lane == 0 && x0 > 0) {
            xm_i = __ldg(img + idx - 1);
            xm_r = __ldg(ref + idx - 1);
        }
        if (lane == 31 && x0 + 2 < N) {
            xp_i = __ldg(img + idx + 2);
            xp_r = __ldg(ref + idx + 2);
        }

        // y neighbors (float2)
        float2 ypi = (y < N - 1) ? __ldg((const float2*)(img + idx + N)) : make_float2(0.f,0.f);
        float2 ymi = (y > 0)     ? __ldg((const float2*)(img + idx - N)) : make_float2(0.f,0.f);
        float2 ypr = (y < N - 1) ? __ldg((const float2*)(ref + idx + N)) : make_float2(0.f,0.f);
        float2 ymr = (y > 0)     ? __ldg((const float2*)(ref + idx - N)) : make_float2(0.f,0.f);

        float2 od, oh, ow;

#pragma unroll
        for (int v = 0; v < 2; v++) {
            const int xx = x0 + v;
            float sum_i, sum_r, sum_ii, sum_rr, sum_ir;
            if (v == 0) {
                sum_i  = A4[0].x + A4[1].x + A4[2].x + A4[3].x + A4[4].x;
                sum_r  = A4[0].y + A4[1].y + A4[2].y + A4[3].y + A4[4].y;
                sum_ii = A4[0].z + A4[1].z + A4[2].z + A4[3].z + A4[4].z;
                sum_rr = A4[0].w + A4[1].w + A4[2].w + A4[3].w + A4[4].w;
                sum_ir = S1[0].x + S1[1].x + S1[2].x + S1[3].x + S1[4].x;
            } else {
                sum_i  = B4[0].x + B4[1].x + B4[2].x + B4[3].x + B4[4].x;
                sum_r  = B4[0].y + B4[1].y + B4[2].y + B4[3].y + B4[4].y;
                sum_ii = B4[0].z + B4[1].z + B4[2].z + B4[3].z + B4[4].z;
                sum_rr = B4[0].w + B4[1].w + B4[2].w + B4[3].w + B4[4].w;
                sum_ir = S1[0].y + S1[1].y + S1[2].y + S1[3].y + S1[4].y;
            }

            const float mi = sum_i * inv_npix;
            const float mr = mi;   // faithful to reference bug

            const float var_r = sum_rr - 2.0f * mr * sum_r + npix * mr * mr;
            const float var_i = sum_ii - 2.0f * mi * sum_i + npix * mi * mi;
            const float cross = sum_ir - mr * sum_i - mi * sum_r + npix * mi * mr;

            const float ci = (v == 0) ? Ci[1].x : Ci[1].y;
            const float cr = (v == 0) ? Cr[1].x : Cr[1].y;
            const float xli = (v == 0) ? xm_i : Ci[1].x;   // x-1 value
            const float xlr = (v == 0) ? xm_r : Cr[1].x;
            const float xri = (v == 0) ? Ci[1].y : xp_i;   // x+1 value
            const float xrr = (v == 0) ? Cr[1].y : xp_r;
            const float yli = (v == 0) ? ymi.x : ymi.y;
            const float ylr = (v == 0) ? ymr.x : ymr.y;
            const float yri = (v == 0) ? ypi.x : ypi.y;
            const float yrr = (v == 0) ? ypr.x : ypr.y;
            const float zli = (v == 0) ? Ci[0].x : Ci[0].y;
            const float zlr = (v == 0) ? Cr[0].x : Cr[0].y;
            const float zri = (v == 0) ? Ci[2].x : Ci[2].y;
            const float zrr = (v == 0) ? Cr[2].x : Cr[2].y;

            float gxi, gxr, gyi, gyr, gzi, gzr;
            if (xx == 0)          { gxi = xri - ci; gxr = xrr - cr; }
            else if (xx == N - 1) { gxi = ci - xli; gxr = cr - xlr; }
            else { gxi = 0.5f * (xri - xli); gxr = 0.5f * (xrr - xlr); }

            if (y == 0)           { gyi = yri - ci; gyr = yrr - cr; }
            else if (y == N - 1)  { gyi = ci - yli; gyr = cr - ylr; }
            else { gyi = 0.5f * (yri - yli); gyr = 0.5f * (yrr - ylr); }

            if (z == 0)           { gzi = zri - ci; gzr = zrr - cr; }
            else if (z == N - 1)  { gzi = ci - zli; gzr = cr - zlr; }
            else { gzi = 0.5f * (zri - zli); gzr = 0.5f * (zrr - zlr); }

            const float gd = 0.5f * (gzi + gzr);
            const float gh = 0.5f * (gyi + gyr);
            const float gw = 0.5f * (gxi + gxr);

            const float factor =
                2.0f * cross / (var_i * var_r + 1e-6f) * (ci - cross / var_r * cr);

            if (v == 0) { od.x = -factor * gd; oh.x = -factor * gh; ow.x = -factor * gw; }
            else        { od.y = -factor * gd; oh.y = -factor * gh; ow.y = -factor * gw; }
        }

        *(float2*)(out + idx)             = od;
        *(float2*)(out + NVOX + idx)      = oh;
        *(float2*)(out + 2u * NVOX + idx) = ow;
    }
}

// ---------------------------------------------------------------------------
extern "C" void kernel_launch(void* const* d_in, const int* in_sizes, int n_in,
                              void* d_out, int out_size)
{
    const float* img = (const float*)d_in[0];   // image
    const float* ref = (const float*)d_in[2];   // reference_image
    float* out = (float*)d_out;

    marker_kernel<<<1, 1>>>();   // parity shim so ncu -s 5 lands on boxxy_kernel
    {
        dim3 block(256, 1, 1);
        dim3 grid(N, N / K1_YC, 1);
        boxxy_kernel<<<grid, block>>>(img, ref);
    }
    {
        dim3 block(256, 1, 1);
        dim3 grid(N / 2, N / K2_ZC, 1);
        zbox_final_kernel<<<grid, block>>>(img, ref, out);
    }
    marker_kernel<<<1, 1>>>();
}

// round 6
// speedup vs baseline: 1.0332x; 1.0332x over previous
#include <cuda_runtime.h>
#include <cstdint>

#define N 256
#define NP 65536u
#define NVOX 16777216u

// Packed xy-box intermediates: float4{sum_i,sum_r,sum_ii,sum_rr} + float{sum_ir}
__device__ float4 g_sum4[16777216];
__device__ float  g_sum1[16777216];

__global__ void marker_kernel() {}

// ===========================================================================
// Kernel 1: 5x5 box in X (warp shuffles) and Y (per-thread register ring).
// One-row-ahead register prefetch hides load latency.
// ===========================================================================
#define K1_YC 64

__global__ __launch_bounds__(256) void boxxy_kernel(
    const float* __restrict__ img, const float* __restrict__ ref)
{
    const unsigned FULL = 0xFFFFFFFFu;
    const int lane = threadIdx.x & 31;
    const int x = threadIdx.x;                 // 0..255 (warp spans 32 x)
    const int z = blockIdx.x;
    const int y0 = blockIdx.y * K1_YC;
    const unsigned zoff = (unsigned)z * NP;

    const bool lm2 = (lane < 2);
    const bool lm1 = (lane == 0);
    const bool lp2 = (lane >= 30);
    const bool lp1 = (lane == 31);

    float qi[5], qr[5], qii[5], qrr[5], qir[5];
#pragma unroll
    for (int k = 0; k < 5; k++) qi[k] = qr[k] = qii[k] = qrr[k] = qir[k] = 0.f;

    // --- prefetch row t=0 (y = y0-2) ---
    float p_vi, p_vr, p_m2i, p_m1i, p_p2i, p_p1i, p_m2r, p_m1r, p_p2r, p_p1r;
    {
        const int yy = y0 - 2;
        const bool in = (yy >= 0);
        const unsigned rb = zoff + (unsigned)(in ? yy : 0) * N;
        p_vi  = in ? __ldg(img + rb + x) : 0.f;
        p_vr  = in ? __ldg(ref + rb + x) : 0.f;
        p_m2i = (lm2 && in && x >= 2)    ? __ldg(img + rb + x - 2) : 0.f;
        p_m1i = (lm1 && in && x >= 1)    ? __ldg(img + rb + x - 1) : 0.f;
        p_p2i = (lp2 && in && x + 2 < N) ? __ldg(img + rb + x + 2) : 0.f;
        p_p1i = (lp1 && in && x + 1 < N) ? __ldg(img + rb + x + 1) : 0.f;
        p_m2r = (lm2 && in && x >= 2)    ? __ldg(ref + rb + x - 2) : 0.f;
        p_m1r = (lm1 && in && x >= 1)    ? __ldg(ref + rb + x - 1) : 0.f;
        p_p2r = (lp2 && in && x + 2 < N) ? __ldg(ref + rb + x + 2) : 0.f;
        p_p1r = (lp1 && in && x + 1 < N) ? __ldg(ref + rb + x + 1) : 0.f;
    }

    for (int t = 0; t < K1_YC + 4; ++t) {
        // consume prefetched row
        const float vi = p_vi, vr = p_vr;
        const float e_m2i = p_m2i, e_m1i = p_m1i, e_p2i = p_p2i, e_p1i = p_p1i;
        const float e_m2r = p_m2r, e_m1r = p_m1r, e_p2r = p_p2r, e_p1r = p_p1r;

        // issue prefetch for next row
        if (t + 1 < K1_YC + 4) {
            const int yy = y0 - 1 + t;
            const bool in = (yy >= 0) & (yy < N);
            const unsigned rb = zoff + (unsigned)(in ? yy : 0) * N;
            p_vi  = in ? __ldg(img + rb + x) : 0.f;
            p_vr  = in ? __ldg(ref + rb + x) : 0.f;
            p_m2i = (lm2 && in && x >= 2)    ? __ldg(img + rb + x - 2) : 0.f;
            p_m1i = (lm1 && in && x >= 1)    ? __ldg(img + rb + x - 1) : 0.f;
            p_p2i = (lp2 && in && x + 2 < N) ? __ldg(img + rb + x + 2) : 0.f;
            p_p1i = (lp1 && in && x + 1 < N) ? __ldg(img + rb + x + 1) : 0.f;
            p_m2r = (lm2 && in && x >= 2)    ? __ldg(ref + rb + x - 2) : 0.f;
            p_m1r = (lm1 && in && x >= 1)    ? __ldg(ref + rb + x - 1) : 0.f;
            p_p2r = (lp2 && in && x + 2 < N) ? __ldg(ref + rb + x + 2) : 0.f;
            p_p1r = (lp1 && in && x + 1 < N) ? __ldg(ref + rb + x + 1) : 0.f;
        }

        float vim1 = __shfl_up_sync(FULL, vi, 1);
        float vim2 = __shfl_up_sync(FULL, vi, 2);
        float vip1 = __shfl_down_sync(FULL, vi, 1);
        float vip2 = __shfl_down_sync(FULL, vi, 2);
        float rim1 = __shfl_up_sync(FULL, vr, 1);
        float rim2 = __shfl_up_sync(FULL, vr, 2);
        float rip1 = __shfl_down_sync(FULL, vr, 1);
        float rip2 = __shfl_down_sync(FULL, vr, 2);

        if (lm2) { vim2 = e_m2i; rim2 = e_m2r; }
        if (lm1) { vim1 = e_m1i; rim1 = e_m1r; }
        if (lp2) { vip2 = e_p2i; rip2 = e_p2r; }
        if (lp1) { vip1 = e_p1i; rip1 = e_p1r; }

        const float s_i  = vim2 + vim1 + vi + vip1 + vip2;
        const float s_r  = rim2 + rim1 + vr + rip1 + rip2;
        const float s_ii = vim2*vim2 + vim1*vim1 + vi*vi + vip1*vip1 + vip2*vip2;
        const float s_rr = rim2*rim2 + rim1*rim1 + vr*vr + rip1*rip1 + rip2*rip2;
        const float s_ir = vim2*rim2 + vim1*rim1 + vi*vr + vip1*rip1 + vip2*rip2;

#pragma unroll
        for (int k = 0; k < 4; k++) {
            qi[k] = qi[k+1]; qr[k] = qr[k+1]; qii[k] = qii[k+1];
            qrr[k] = qrr[k+1]; qir[k] = qir[k+1];
        }
        qi[4] = s_i; qr[4] = s_r; qii[4] = s_ii; qrr[4] = s_rr; qir[4] = s_ir;

        if (t >= 4) {
            const unsigned o = zoff + (unsigned)(y0 + t - 4) * N + (unsigned)x;
            float4 v;
            v.x = qi[0] + qi[1] + qi[2] + qi[3] + qi[4];
            v.y = qr[0] + qr[1] + qr[2] + qr[3] + qr[4];
            v.z = qii[0] + qii[1] + qii[2] + qii[3] + qii[4];
            v.w = qrr[0] + qrr[1] + qrr[2] + qrr[3] + qrr[4];
            g_sum4[o] = v;
            g_sum1[o] = qir[0] + qir[1] + qir[2] + qir[3] + qir[4];
        }
    }
}

// ===========================================================================
// Kernel 2: z-box + gradients + force epilogue. 2 voxels (x pair) per thread,
// one-plane-ahead register prefetch, 5-deep register rings.
// CTA: 256 threads = 2 y-rows x 128 x-pairs. Marches 32-plane z chunk.
// ===========================================================================
#define K2_ZC 32

__global__ __launch_bounds__(256, 2) void zbox_final_kernel(
    const float* __restrict__ img, const float* __restrict__ ref,
    float* __restrict__ out)
{
    const unsigned FULL = 0xFFFFFFFFu;
    const int tid  = threadIdx.x;
    const int lane = tid & 31;
    const int xi   = tid & 127;          // x-pair index, 0..127
    const int x0   = xi << 1;            // first x of pair
    const int y    = (blockIdx.x << 1) + (tid >> 7);
    const int z0   = blockIdx.y * K2_ZC;
    const unsigned base = (unsigned)y * N + (unsigned)x0;

    const float npix = 125.0f;
    const float inv_npix = 1.0f / 125.0f;

    float4 A4[5], B4[5];      // sums for x0, x0+1
    float2 S1[5];             // sum_ir pair
    float2 Ci[3], Cr[3];      // center pairs: planes z-1, z, z+1 (after shift)

    // prologue: slots 1..4 = planes z0-2 .. z0+1
#pragma unroll
    for (int k = 0; k < 4; k++) {
        int zz = z0 - 2 + k;
        bool in = (zz >= 0) & (zz < N);
        unsigned o = (unsigned)(in ? zz : 0) * NP + base;
        A4[k+1] = in ? __ldg(&g_sum4[o])     : make_float4(0.f,0.f,0.f,0.f);
        B4[k+1] = in ? __ldg(&g_sum4[o + 1]) : make_float4(0.f,0.f,0.f,0.f);
        S1[k+1] = in ? *(const float2*)&g_sum1[o] : make_float2(0.f,0.f);
    }
    {
        bool inm = (z0 - 1) >= 0;
        unsigned om = (unsigned)(inm ? (z0 - 1) : 0) * NP + base;
        Ci[1] = inm ? __ldg((const float2*)(img + om)) : make_float2(0.f,0.f);
        Cr[1] = inm ? __ldg((const float2*)(ref + om)) : make_float2(0.f,0.f);
        unsigned oc = (unsigned)z0 * NP + base;
        Ci[2] = __ldg((const float2*)(img + oc));
        Cr[2] = __ldg((const float2*)(ref + oc));
    }
    // pending: sums plane z0+2, centers plane z0+1
    float4 pA, pB; float2 pS, pCi, pCr;
    {
        int zz = z0 + 2;
        bool in = zz < N;
        unsigned o = (unsigned)(in ? zz : 0) * NP + base;
        pA = in ? __ldg(&g_sum4[o])     : make_float4(0.f,0.f,0.f,0.f);
        pB = in ? __ldg(&g_sum4[o + 1]) : make_float4(0.f,0.f,0.f,0.f);
        pS = in ? *(const float2*)&g_sum1[o] : make_float2(0.f,0.f);
        int zc = z0 + 1;
        bool inc = zc < N;
        unsigned oc = (unsigned)(inc ? zc : 0) * NP + base;
        pCi = inc ? __ldg((const float2*)(img + oc)) : make_float2(0.f,0.f);
        pCr = inc ? __ldg((const float2*)(ref + oc)) : make_float2(0.f,0.f);
    }

    for (int z = z0; z < z0 + K2_ZC; ++z) {
        // shift rings, consume pending
#pragma unroll
        for (int k = 0; k < 4; k++) { A4[k] = A4[k+1]; B4[k] = B4[k+1]; S1[k] = S1[k+1]; }
        A4[4] = pA; B4[4] = pB; S1[4] = pS;
        Ci[0] = Ci[1]; Ci[1] = Ci[2]; Ci[2] = pCi;
        Cr[0] = Cr[1]; Cr[1] = Cr[2]; Cr[2] = pCr;

        // issue prefetch for next iteration (sums z+3, centers z+2)
        {
            int zz = z + 3;
            bool in = zz < N;
            unsigned o = (unsigned)(in ? zz : 0) * NP + base;
            pA = in ? __ldg(&g_sum4[o])     : make_float4(0.f,0.f,0.f,0.f);
            pB = in ? __ldg(&g_sum4[o + 1]) : make_float4(0.f,0.f,0.f,0.f);
            pS = in ? *(const float2*)&g_sum1[o] : make_float2(0.f,0.f);
            int zc = z + 2;
            bool inc = zc < N;
            unsigned oc = (unsigned)(inc ? zc : 0) * NP + base;
            pCi = inc ? __ldg((const float2*)(img + oc)) : make_float2(0.f,0.f);
            pCr = inc ? __ldg((const float2*)(ref + oc)) : make_float2(0.f,0.f);
        }

        const unsigned idx = (unsigned)z * NP + base;

        // x-neighbor values outside the pair via shuffle; warp-edge lanes load
        float xm_i = __shfl_up_sync(FULL, Ci[1].y, 1);
        float xm_r = __shfl_up_sync(FULL, Cr[1].y, 1);
        float xp_i = __shfl_down_sync(FULL, Ci[1].x, 1);
        float xp_r = __shfl_down_sync(FULL, Cr[1].x, 1);
        if (lane == 0 && x0 > 0) {
            xm_i = __ldg(img + idx - 1);
            xm_r = __ldg(ref + idx - 1);
        }
        if (lane == 31 && x0 + 2 < N) {
            xp_i = __ldg(img + idx + 2);
            xp_r = __ldg(ref + idx + 2);
        }

        // y neighbors (float2)
        float2 ypi = (y < N - 1) ? __ldg((const float2*)(img + idx + N)) : make_float2(0.f,0.f);
        float2 ymi = (y > 0)     ? __ldg((const float2*)(img + idx - N)) : make_float2(0.f,0.f);
        float2 ypr = (y < N - 1) ? __ldg((const float2*)(ref + idx + N)) : make_float2(0.f,0.f);
        float2 ymr = (y > 0)     ? __ldg((const float2*)(ref + idx - N)) : make_float2(0.f,0.f);

        float2 od, oh, ow;

#pragma unroll
        for (int v = 0; v < 2; v++) {
            const int xx = x0 + v;
            float sum_i, sum_r, sum_ii, sum_rr, sum_ir;
            if (v == 0) {
                sum_i  = A4[0].x + A4[1].x + A4[2].x + A4[3].x + A4[4].x;
                sum_r  = A4[0].y + A4[1].y + A4[2].y + A4[3].y + A4[4].y;
                sum_ii = A4[0].z + A4[1].z + A4[2].z + A4[3].z + A4[4].z;
                sum_rr = A4[0].w + A4[1].w + A4[2].w + A4[3].w + A4[4].w;
                sum_ir = S1[0].x + S1[1].x + S1[2].x + S1[3].x + S1[4].x;
            } else {
                sum_i  = B4[0].x + B4[1].x + B4[2].x + B4[3].x + B4[4].x;
                sum_r  = B4[0].y + B4[1].y + B4[2].y + B4[3].y + B4[4].y;
                sum_ii = B4[0].z + B4[1].z + B4[2].z + B4[3].z + B4[4].z;
                sum_rr = B4[0].w + B4[1].w + B4[2].w + B4[3].w + B4[4].w;
                sum_ir = S1[0].y + S1[1].y + S1[2].y + S1[3].y + S1[4].y;
            }

            const float mi = sum_i * inv_npix;
            const float mr = mi;   // faithful to reference bug

            const float var_r = sum_rr - 2.0f * mr * sum_r + npix * mr * mr;
            const float var_i = sum_ii - 2.0f * mi * sum_i + npix * mi * mi;
            const float cross = sum_ir - mr * sum_i - mi * sum_r + npix * mi * mr;

            const float ci = (v == 0) ? Ci[1].x : Ci[1].y;
            const float cr = (v == 0) ? Cr[1].x : Cr[1].y;
            const float xli = (v == 0) ? xm_i : Ci[1].x;   // x-1 value
            const float xlr = (v == 0) ? xm_r : Cr[1].x;
            const float xri = (v == 0) ? Ci[1].y : xp_i;   // x+1 value
            const float xrr = (v == 0) ? Cr[1].y : xp_r;
            const float yli = (v == 0) ? ymi.x : ymi.y;
            const float ylr = (v == 0) ? ymr.x : ymr.y;
            const float yri = (v == 0) ? ypi.x : ypi.y;
            const float yrr = (v == 0) ? ypr.x : ypr.y;
            const float zli = (v == 0) ? Ci[0].x : Ci[0].y;
            const float zlr = (v == 0) ? Cr[0].x : Cr[0].y;
            const float zri = (v == 0) ? Ci[2].x : Ci[2].y;
            const float zrr = (v == 0) ? Cr[2].x : Cr[2].y;

            float gxi, gxr, gyi, gyr, gzi, gzr;
            if (xx == 0)          { gxi = xri - ci; gxr = xrr - cr; }
            else if (xx == N - 1) { gxi = ci - xli; gxr = cr - xlr; }
            else { gxi = 0.5f * (xri - xli); gxr = 0.5f * (xrr - xlr); }

            if (y == 0)           { gyi = yri - ci; gyr = yrr - cr; }
            else if (y == N - 1)  { gyi = ci - yli; gyr = cr - ylr; }
            else { gyi = 0.5f * (yri - yli); gyr = 0.5f * (yrr - ylr); }

            if (z == 0)           { gzi = zri - ci; gzr = zrr - cr; }
            else if (z == N - 1)  { gzi = ci - zli; gzr = cr - zlr; }
            else { gzi = 0.5f * (zri - zli); gzr = 0.5f * (zrr - zlr); }

            const float gd = 0.5f * (gzi + gzr);
            const float gh = 0.5f * (gyi + gyr);
            const float gw = 0.5f * (gxi + gxr);

            const float factor =
                2.0f * cross / (var_i * var_r + 1e-6f) * (ci - cross / var_r * cr);

            if (v == 0) { od.x = -factor * gd; oh.x = -factor * gh; ow.x = -factor * gw; }
            else        { od.y = -factor * gd; oh.y = -factor * gh; ow.y = -factor * gw; }
        }

        *(float2*)(out + idx)             = od;
        *(float2*)(out + NVOX + idx)      = oh;
        *(float2*)(out + 2u * NVOX + idx) = ow;
    }
}

// ---------------------------------------------------------------------------
extern "C" void kernel_launch(void* const* d_in, const int* in_sizes, int n_in,
                              void* d_out, int out_size)
{
    const float* img = (const float*)d_in[0];   // image
    const float* ref = (const float*)d_in[2];   // reference_image
    float* out = (float*)d_out;

    marker_kernel<<<1, 1>>>();   // parity shim so ncu -s 5 lands on boxxy_kernel
    {
        dim3 block(256, 1, 1);
        dim3 grid(N, N / K1_YC, 1);
        boxxy_kernel<<<grid, block>>>(img, ref);
    }
    {
        dim3 block(256, 1, 1);
        dim3 grid(N / 2, N / K2_ZC, 1);
        zbox_final_kernel<<<grid, block>>>(img, ref, out);
    }
    marker_kernel<<<1, 1>>>();
}

// round 7
// speedup vs baseline: 1.4123x; 1.3670x over previous
#include <cuda_runtime.h>
#include <cstdint>

#define N 256
#define NP 65536u
#define NVOX 16777216u
#define YC 64
#define TPB 256

// ===========================================================================
// Fully fused NCC forces: CTA spans full x-row at fixed z, marches y.
// Per step: load 5 z-plane rows -> z-summed quantities -> smem x-box ->
// register y-ring -> epilogue.
// ===========================================================================
__global__ __launch_bounds__(TPB, 2) void ncc_fused_kernel(
    const float* __restrict__ img, const float* __restrict__ ref,
    float* __restrict__ out)
{
    __shared__ float qz[2][5][N + 4];     // double-buffered x-padded quantity rows
    __shared__ float crow[4][2][N + 2];   // center-row ring (img/ref), x-padded

    const int x  = threadIdx.x;
    const int z  = blockIdx.x;
    const int y0 = blockIdx.y * YC;

    // zero the pads once (never rewritten)
    if (x < 40) {
        int b = x / 20, rem = x % 20, q = rem / 4, p = rem % 4;
        int xi = (p < 2) ? p : (N + p);
        qz[b][q][xi] = 0.f;
    }
    if (x < 16) {
        int rr = x >> 2, a = (x >> 1) & 1, s = x & 1;
        crow[rr][a][s ? (N + 1) : 0] = 0.f;
    }

    const float npix = 125.0f;
    const float inv_npix = 1.0f / 125.0f;

    // y-rings of x,z-boxed quantities
    float ring_i[5] = {0,0,0,0,0}, ring_r[5] = {0,0,0,0,0},
          ring_ii[5] = {0,0,0,0,0}, ring_rr[5] = {0,0,0,0,0},
          ring_ir[5] = {0,0,0,0,0};
    // center rings for gradients: plane z (depth 4), planes z±1 (depth 3)
    float ci_r[4] = {0,0,0,0}, cr_r[4] = {0,0,0,0};
    float zpi_r[3] = {0,0,0}, zpr_r[3] = {0,0,0};
    float zmi_r[3] = {0,0,0}, zmr_r[3] = {0,0,0};

    // per-plane bases (uniform across CTA)
    bool pz[5];
    unsigned pbase[5];
#pragma unroll
    for (int p = 0; p < 5; p++) {
        int zz = z - 2 + p;
        pz[p] = (zz >= 0) && (zz < N);
        pbase[p] = (unsigned)(pz[p] ? zz : 0) * NP + (unsigned)x;
    }

    // prefetch row t=0 (y = y0-2)
    float pvi[5], pvr[5];
    {
        int yl = y0 - 2;
        bool in = (yl >= 0);
        unsigned ro = (unsigned)(in ? yl : 0) * N;
#pragma unroll
        for (int p = 0; p < 5; p++) {
            bool ok = in && pz[p];
            pvi[p] = ok ? __ldg(img + pbase[p] + ro) : 0.f;
            pvr[p] = ok ? __ldg(ref + pbase[p] + ro) : 0.f;
        }
    }
    __syncthreads();   // pads visible

    for (int t = 0; t < YC + 4; ++t) {
        const int yl  = y0 - 2 + t;
        const int buf = t & 1;

        // z-summed quantities from prefetched row
        const float vi0 = pvi[0], vi1 = pvi[1], vi2 = pvi[2], vi3 = pvi[3], vi4 = pvi[4];
        const float vr0 = pvr[0], vr1 = pvr[1], vr2 = pvr[2], vr3 = pvr[3], vr4 = pvr[4];
        const float qi  = vi0 + vi1 + vi2 + vi3 + vi4;
        const float qr  = vr0 + vr1 + vr2 + vr3 + vr4;
        const float qii = vi0*vi0 + vi1*vi1 + vi2*vi2 + vi3*vi3 + vi4*vi4;
        const float qrr = vr0*vr0 + vr1*vr1 + vr2*vr2 + vr3*vr3 + vr4*vr4;
        const float qir = vi0*vr0 + vi1*vr1 + vi2*vr2 + vi3*vr3 + vi4*vr4;

        qz[buf][0][x + 2] = qi;
        qz[buf][1][x + 2] = qr;
        qz[buf][2][x + 2] = qii;
        qz[buf][3][x + 2] = qrr;
        qz[buf][4][x + 2] = qir;
        crow[t & 3][0][x + 1] = vi2;
        crow[t & 3][1][x + 1] = vr2;

        // push center rings
#pragma unroll
        for (int k = 0; k < 3; k++) { ci_r[k] = ci_r[k+1]; cr_r[k] = cr_r[k+1]; }
        ci_r[3] = vi2; cr_r[3] = vr2;
#pragma unroll
        for (int k = 0; k < 2; k++) {
            zpi_r[k] = zpi_r[k+1]; zpr_r[k] = zpr_r[k+1];
            zmi_r[k] = zmi_r[k+1]; zmr_r[k] = zmr_r[k+1];
        }
        zpi_r[2] = vi3; zpr_r[2] = vr3;
        zmi_r[2] = vi1; zmr_r[2] = vr1;

        // prefetch next row (lands during this step's compute)
        if (t + 1 < YC + 4) {
            int yn = yl + 1;
            bool in = (yn >= 0) && (yn < N);
            unsigned ro = (unsigned)(in ? yn : 0) * N;
#pragma unroll
            for (int p = 0; p < 5; p++) {
                bool ok = in && pz[p];
                pvi[p] = ok ? __ldg(img + pbase[p] + ro) : 0.f;
                pvr[p] = ok ? __ldg(ref + pbase[p] + ro) : 0.f;
            }
        }
        __syncthreads();

        // x-box of this row's quantities (padded smem: no edge branches)
        float bi = 0.f, br = 0.f, bii = 0.f, brr = 0.f, bir = 0.f;
#pragma unroll
        for (int d = 0; d < 5; d++) {
            bi  += qz[buf][0][x + d];
            br  += qz[buf][1][x + d];
            bii += qz[buf][2][x + d];
            brr += qz[buf][3][x + d];
            bir += qz[buf][4][x + d];
        }
        // push y-rings
#pragma unroll
        for (int k = 0; k < 4; k++) {
            ring_i[k] = ring_i[k+1]; ring_r[k] = ring_r[k+1];
            ring_ii[k] = ring_ii[k+1]; ring_rr[k] = ring_rr[k+1];
            ring_ir[k] = ring_ir[k+1];
        }
        ring_i[4] = bi; ring_r[4] = br; ring_ii[4] = bii;
        ring_rr[4] = brr; ring_ir[4] = bir;

        // epilogue for y = yl - 2
        if (t >= 4) {
            const int y = yl - 2;

            const float sum_i  = ring_i[0] + ring_i[1] + ring_i[2] + ring_i[3] + ring_i[4];
            const float sum_r  = ring_r[0] + ring_r[1] + ring_r[2] + ring_r[3] + ring_r[4];
            const float sum_ii = ring_ii[0] + ring_ii[1] + ring_ii[2] + ring_ii[3] + ring_ii[4];
            const float sum_rr = ring_rr[0] + ring_rr[1] + ring_rr[2] + ring_rr[3] + ring_rr[4];
            const float sum_ir = ring_ir[0] + ring_ir[1] + ring_ir[2] + ring_ir[3] + ring_ir[4];

            // faithful to reference: reference mean uses sum_i
            const float mi = sum_i * inv_npix;
            const float mr = mi;

            const float var_r = sum_rr - 2.0f * mr * sum_r + npix * mr * mr;
            const float var_i = sum_ii - 2.0f * mi * sum_i + npix * mi * mi;
            const float cross = sum_ir - mr * sum_i - mi * sum_r + npix * mi * mr;

            // centers: ci at row y (slot 1); y±1 at slots 2 / 0; z±1 at slot 0
            const float ci = ci_r[1], cr = cr_r[1];
            const int rs = (t - 2) & 3;
            const float xim = crow[rs][0][x];       // x-1
            const float xip = crow[rs][0][x + 2];   // x+1
            const float xrm = crow[rs][1][x];
            const float xrp = crow[rs][1][x + 2];

            float gxi, gxr, gyi, gyr, gzi, gzr;
            if (x == 0)          { gxi = xip - ci; gxr = xrp - cr; }
            else if (x == N - 1) { gxi = ci - xim; gxr = cr - xrm; }
            else { gxi = 0.5f * (xip - xim); gxr = 0.5f * (xrp - xrm); }

            if (y == 0)          { gyi = ci_r[2] - ci; gyr = cr_r[2] - cr; }
            else if (y == N - 1) { gyi = ci - ci_r[0]; gyr = cr - cr_r[0]; }
            else { gyi = 0.5f * (ci_r[2] - ci_r[0]); gyr = 0.5f * (cr_r[2] - cr_r[0]); }

            if (z == 0)          { gzi = zpi_r[0] - ci; gzr = zpr_r[0] - cr; }
            else if (z == N - 1) { gzi = ci - zmi_r[0]; gzr = cr - zmr_r[0]; }
            else { gzi = 0.5f * (zpi_r[0] - zmi_r[0]); gzr = 0.5f * (zpr_r[0] - zmr_r[0]); }

            const float gd = 0.5f * (gzi + gzr);
            const float gh = 0.5f * (gyi + gyr);
            const float gw = 0.5f * (gxi + gxr);

            const float factor = 2.0f * cross
                * __fdividef(1.0f, var_i * var_r + 1e-6f)
                * (ci - __fdividef(cross, var_r) * cr);

            const unsigned idx = (unsigned)z * NP + (unsigned)y * N + (unsigned)x;
            out[idx]             = -factor * gd;
            out[NVOX + idx]      = -factor * gh;
            out[2u * NVOX + idx] = -factor * gw;
        }
    }
}

// ---------------------------------------------------------------------------
extern "C" void kernel_launch(void* const* d_in, const int* in_sizes, int n_in,
                              void* d_out, int out_size)
{
    const float* img = (const float*)d_in[0];   // image
    const float* ref = (const float*)d_in[2];   // reference_image
    float* out = (float*)d_out;

    dim3 block(TPB, 1, 1);
    dim3 grid(N, N / YC, 1);    // 256 z  x  4 y-chunks
    ncc_fused_kernel<<<grid, block>>>(img, ref, out);
}

// round 8
// speedup vs baseline: 1.9635x; 1.3903x over previous
#include <cuda_runtime.h>
#include <cstdint>

#define N 256
#define NP 65536u
#define NVOX 16777216u
#define YC 64
#define NSTEPS 70            // 14 * 5; epilogue at t in [4,67]

// ---------------- packed f32x2 helpers (sm_103a) ----------------
union F2U { float2 f; unsigned long long u; };
__device__ __forceinline__ float2 f2add(float2 a, float2 b) {
    F2U x, y, r; x.f = a; y.f = b;
    asm("add.rn.f32x2 %0,%1,%2;" : "=l"(r.u) : "l"(x.u), "l"(y.u));
    return r.f;
}
__device__ __forceinline__ float2 f2mul(float2 a, float2 b) {
    F2U x, y, r; x.f = a; y.f = b;
    asm("mul.rn.f32x2 %0,%1,%2;" : "=l"(r.u) : "l"(x.u), "l"(y.u));
    return r.f;
}
__device__ __forceinline__ float2 f2fma(float2 a, float2 b, float2 c) {
    F2U x, y, zc, r; x.f = a; y.f = b; zc.f = c;
    asm("fma.rn.f32x2 %0,%1,%2,%3;" : "=l"(r.u) : "l"(x.u), "l"(y.u), "l"(zc.u));
    return r.f;
}
__device__ __forceinline__ float2 f2set(float a, float b) { float2 r; r.x = a; r.y = b; return r; }

// ===========================================================================
// Fused NCC forces, 2 voxels/thread. CTA = 128 threads spanning full x-row
// at fixed z; marches y. Per step: 10 LDG.64 (5 z-planes, img+ref) ->
// packed z-summed quantities -> smem x-box -> running y-sums (static ring) ->
// packed epilogue.
// ===========================================================================
__global__ __launch_bounds__(128, 4) void ncc_fused2_kernel(
    const float* __restrict__ img, const float* __restrict__ ref,
    float* __restrict__ out)
{
    __shared__ float qz[2][5][264];   // double-buffered z-summed quantity rows, x-pad 2
    __shared__ float cc[5][6][260];   // 5-slot row ring: {ci, cr, zpi, zpr, zmi, zmr}

    const int t0 = threadIdx.x;       // 0..127
    const int x0 = t0 << 1;           // first x of pair
    const int z  = blockIdx.x;
    const int y0 = blockIdx.y * YC;

    // zero qz pads (idx 0,1,258,259 for both buffers, all 5 quantities)
    if (t0 < 40) {
        int b = t0 / 20, rem = t0 % 20, q = rem / 4, p = rem & 3;
        int xi = (p < 2) ? p : (256 + p);
        qz[b][q][xi] = 0.f;
    }

    bool pz[5]; unsigned pb[5];
#pragma unroll
    for (int p = 0; p < 5; p++) {
        int zz = z - 2 + p;
        pz[p] = (zz >= 0) && (zz < N);
        pb[p] = (unsigned)(pz[p] ? zz : 0) * NP + (unsigned)x0;
    }

    const float2 zero2 = f2set(0.f, 0.f);
    const float2 km1   = f2set(-1.f, -1.f);
    const float2 km2   = f2set(-2.f, -2.f);
    const float2 k05   = f2set(0.5f, 0.5f);
    const float2 k2    = f2set(2.f, 2.f);
    const float2 k125  = f2set(125.f, 125.f);
    const float2 kinv  = f2set(1.f / 125.f, 1.f / 125.f);
    const float2 keps  = f2set(1e-6f, 1e-6f);

    float2 ring[5][5];                // boxed-quantity y-ring (static idx)
    float2 sums[5];                   // running 5-row sums
#pragma unroll
    for (int q = 0; q < 5; q++) {
        sums[q] = zero2;
#pragma unroll
        for (int k = 0; k < 5; k++) ring[q][k] = zero2;
    }

    // prefetch row t=0 (yl = y0-2)
    float2 pvi[5], pvr[5];
    {
        int yl = y0 - 2;
        bool inr = (yl >= 0);
        unsigned ro = (unsigned)(inr ? yl : 0) * N;
#pragma unroll
        for (int p = 0; p < 5; p++) {
            bool ok = inr && pz[p];
            pvi[p] = ok ? __ldg((const float2*)(img + pb[p] + ro)) : zero2;
            pvr[p] = ok ? __ldg((const float2*)(ref + pb[p] + ro)) : zero2;
        }
    }
    __syncthreads();

    int buf = 0;
    for (int tb = 0; tb < 14; ++tb) {
#pragma unroll
        for (int j = 0; j < 5; ++j) {
            const int t = tb * 5 + j;

            // ---- z-summed quantities (packed) ----
            const float2 v0 = pvi[0], v1 = pvi[1], v2 = pvi[2], v3 = pvi[3], v4 = pvi[4];
            const float2 r0 = pvr[0], r1 = pvr[1], r2 = pvr[2], r3 = pvr[3], r4 = pvr[4];
            const float2 qi  = f2add(f2add(f2add(v0, v1), f2add(v2, v3)), v4);
            const float2 qr  = f2add(f2add(f2add(r0, r1), f2add(r2, r3)), r4);
            const float2 qii = f2fma(v4, v4, f2fma(v3, v3, f2fma(v2, v2, f2fma(v1, v1, f2mul(v0, v0)))));
            const float2 qrr = f2fma(r4, r4, f2fma(r3, r3, f2fma(r2, r2, f2fma(r1, r1, f2mul(r0, r0)))));
            const float2 qir = f2fma(v4, r4, f2fma(v3, r3, f2fma(v2, r2, f2fma(v1, r1, f2mul(v0, r0)))));

            *(float2*)&qz[buf][0][x0 + 2] = qi;
            *(float2*)&qz[buf][1][x0 + 2] = qr;
            *(float2*)&qz[buf][2][x0 + 2] = qii;
            *(float2*)&qz[buf][3][x0 + 2] = qrr;
            *(float2*)&qz[buf][4][x0 + 2] = qir;
            cc[j][0][x0 + 1] = v2.x;  cc[j][0][x0 + 2] = v2.y;   // center row (x-halo 1)
            cc[j][1][x0 + 1] = r2.x;  cc[j][1][x0 + 2] = r2.y;
            *(float2*)&cc[j][2][x0] = v3;    // plane z+1 row
            *(float2*)&cc[j][3][x0] = r3;
            *(float2*)&cc[j][4][x0] = v1;    // plane z-1 row
            *(float2*)&cc[j][5][x0] = r1;

            // ---- prefetch next row (lands during this step's compute) ----
            if (t + 1 < NSTEPS) {
                int yn = y0 - 1 + t;
                bool inr = (yn >= 0) && (yn < N);
                unsigned ro = (unsigned)(inr ? yn : 0) * N;
#pragma unroll
                for (int p = 0; p < 5; p++) {
                    bool ok = inr && pz[p];
                    pvi[p] = ok ? __ldg((const float2*)(img + pb[p] + ro)) : zero2;
                    pvr[p] = ok ? __ldg((const float2*)(ref + pb[p] + ro)) : zero2;
                }
            }
            __syncthreads();

            // ---- x-box + running y-sum update (static ring slot j) ----
#pragma unroll
            for (int q = 0; q < 5; q++) {
                float2 a = *(const float2*)&qz[buf][q][x0];       // x0-2, x0-1
                float2 b = *(const float2*)&qz[buf][q][x0 + 2];   // x0,   x0+1
                float2 c = *(const float2*)&qz[buf][q][x0 + 4];   // x0+2, x0+3
                float s = a.y + b.x + b.y + c.x;
                float2 bx = f2set(s + a.x, s + c.y);
                sums[q] = f2add(sums[q], f2fma(ring[q][j], km1, bx));
                ring[q][j] = bx;
            }
            buf ^= 1;

            // ---- epilogue for y = y0 + t - 4 ----
            if (t >= 4 && t < 68) {
                const int y = y0 + t - 4;
                const int jc = (j + 3) % 5;   // slot of row y
                const int jp = (j + 4) % 5;   // row y+1
                const int jm = (j + 2) % 5;   // row y-1

                const float2 sum_i = sums[0], sum_r = sums[1];
                const float2 sum_ii = sums[2], sum_rr = sums[3], sum_ir = sums[4];

                const float2 mi = f2mul(sum_i, kinv);   // reference mean uses sum_i (faithful)
                const float2 t1 = f2mul(mi, k125);
                const float2 varr = f2fma(mi, f2fma(sum_r, km2, t1), sum_rr);
                const float2 vari = f2fma(mi, f2fma(sum_i, km2, t1), sum_ii);
                const float2 cross = f2fma(mi, f2fma(f2add(sum_i, sum_r), km1, t1), sum_ir);

                // center-row values: p0 = (x0-1, x0), p1 = (x0+1, x0+2)
                const float2 p0i = *(const float2*)&cc[jc][0][x0];
                const float2 p1i = *(const float2*)&cc[jc][0][x0 + 2];
                const float2 p0r = *(const float2*)&cc[jc][1][x0];
                const float2 p1r = *(const float2*)&cc[jc][1][x0 + 2];
                const float2 ciI = f2set(p0i.y, p1i.x);
                const float2 ciR = f2set(p0r.y, p1r.x);

                const float2 ypI = f2set(cc[jp][0][x0 + 1], cc[jp][0][x0 + 2]);
                const float2 ymI = f2set(cc[jm][0][x0 + 1], cc[jm][0][x0 + 2]);
                const float2 ypR = f2set(cc[jp][1][x0 + 1], cc[jp][1][x0 + 2]);
                const float2 ymR = f2set(cc[jm][1][x0 + 1], cc[jm][1][x0 + 2]);
                const float2 zpI = *(const float2*)&cc[jc][2][x0];
                const float2 zpR = *(const float2*)&cc[jc][3][x0];
                const float2 zmI = *(const float2*)&cc[jc][4][x0];
                const float2 zmR = *(const float2*)&cc[jc][5][x0];

                // central differences (packed), one-sided overrides at edges
                float2 gxi = f2mul(f2fma(p0i, km1, p1i), k05);
                float2 gxr = f2mul(f2fma(p0r, km1, p1r), k05);
                float2 gyi = f2mul(f2fma(ymI, km1, ypI), k05);
                float2 gyr = f2mul(f2fma(ymR, km1, ypR), k05);
                float2 gzi = f2mul(f2fma(zmI, km1, zpI), k05);
                float2 gzr = f2mul(f2fma(zmR, km1, zpR), k05);

                if (t0 == 0)   { gxi.x = ciI.y - ciI.x; gxr.x = ciR.y - ciR.x; }
                if (t0 == 127) { gxi.y = ciI.y - ciI.x; gxr.y = ciR.y - ciR.x; }
                if (y == 0)     { gyi = f2fma(ciI, km1, ypI); gyr = f2fma(ciR, km1, ypR); }
                if (y == N - 1) { gyi = f2fma(ymI, km1, ciI); gyr = f2fma(ymR, km1, ciR); }
                if (z == 0)     { gzi = f2fma(ciI, km1, zpI); gzr = f2fma(ciR, km1, zpR); }
                if (z == N - 1) { gzi = f2fma(zmI, km1, ciI); gzr = f2fma(zmR, km1, ciR); }

                const float2 gd = f2mul(f2add(gzi, gzr), k05);
                const float2 gh = f2mul(f2add(gyi, gyr), k05);
                const float2 gw = f2mul(f2add(gxi, gxr), k05);

                const float2 den = f2fma(vari, varr, keps);
                float2 rden, cv;
                rden.x = __fdividef(1.f, den.x);
                rden.y = __fdividef(1.f, den.y);
                cv.x = __fdividef(cross.x, varr.x);
                cv.y = __fdividef(cross.y, varr.y);
                const float2 inner = f2fma(f2mul(cv, km1), ciR, ciI);
                const float2 fac = f2mul(f2mul(k2, cross), f2mul(rden, inner));
                const float2 nfac = f2mul(fac, km1);

                const unsigned idx = (unsigned)z * NP + (unsigned)y * N + (unsigned)x0;
                *(float2*)(out + idx)             = f2mul(nfac, gd);
                *(float2*)(out + NVOX + idx)      = f2mul(nfac, gh);
                *(float2*)(out + 2u * NVOX + idx) = f2mul(nfac, gw);
            }
        }
    }
}

// ---------------------------------------------------------------------------
extern "C" void kernel_launch(void* const* d_in, const int* in_sizes, int n_in,
                              void* d_out, int out_size)
{
    const float* img = (const float*)d_in[0];   // image
    const float* ref = (const float*)d_in[2];   // reference_image
    float* out = (float*)d_out;

    dim3 block(128, 1, 1);
    dim3 grid(N, N / YC, 1);    // 256 z  x  4 y-chunks
    ncc_fused2_kernel<<<grid, block>>>(img, ref, out);
}